// round 1
// baseline (speedup 1.0000x reference)
#include <cuda_runtime.h>
#include <cstdint>

#define N_NODES_MAX 100000
#define IN_CH 256
#define OUT_CH 128

// Scratch for xw = x @ W  (51.2 MB, static device allocation — allowed)
__device__ float g_xw[(size_t)N_NODES_MAX * OUT_CH];

// ---------------------------------------------------------------------------
// GEMM: g_xw[M,128] = A[M,256] * B[256,128], fp32 SIMT tiled
// Block tile 128x128, K-tile 16, 256 threads, 8x8 per-thread microtile.
// ---------------------------------------------------------------------------
__global__ __launch_bounds__(256, 2)
void gemm_kernel(const float* __restrict__ A, const float* __restrict__ B, int M)
{
    __shared__ float As[16][132];   // [k][m], padded to kill store conflicts
    __shared__ float Bs[16][128];   // [k][n]

    const int tid = threadIdx.x;
    const int block_row = blockIdx.x * 128;

    const int tx = tid & 15;        // 0..15  (N direction)
    const int ty = tid >> 4;        // 0..15  (M direction)

    // A tile load mapping: 128 rows x 16 k-cols, 2 x float4 per thread
    const int aRow = tid >> 2;            // 0..63 (second row = +64)
    const int aCol = (tid & 3) * 4;       // 0,4,8,12
    // B tile load mapping: 16 rows x 128 cols, 2 x float4 per thread
    const int bRow = tid >> 5;            // 0..7 (second row = +8)
    const int bCol = (tid & 31) * 4;      // 0..124

    float acc[8][8];
    #pragma unroll
    for (int i = 0; i < 8; ++i)
        #pragma unroll
        for (int j = 0; j < 8; ++j)
            acc[i][j] = 0.0f;

    for (int kt = 0; kt < IN_CH / 16; ++kt) {
        // ---- load A tile (guard M edge) ----
        {
            const int r0 = block_row + aRow;
            const int r1 = r0 + 64;
            float4 a0 = make_float4(0.f, 0.f, 0.f, 0.f);
            float4 a1 = a0;
            if (r0 < M)
                a0 = *reinterpret_cast<const float4*>(A + (size_t)r0 * IN_CH + kt * 16 + aCol);
            if (r1 < M)
                a1 = *reinterpret_cast<const float4*>(A + (size_t)r1 * IN_CH + kt * 16 + aCol);
            As[aCol + 0][aRow]      = a0.x;
            As[aCol + 1][aRow]      = a0.y;
            As[aCol + 2][aRow]      = a0.z;
            As[aCol + 3][aRow]      = a0.w;
            As[aCol + 0][aRow + 64] = a1.x;
            As[aCol + 1][aRow + 64] = a1.y;
            As[aCol + 2][aRow + 64] = a1.z;
            As[aCol + 3][aRow + 64] = a1.w;
        }
        // ---- load B tile ----
        {
            const float4 b0 = *reinterpret_cast<const float4*>(B + (size_t)(kt * 16 + bRow) * OUT_CH + bCol);
            const float4 b1 = *reinterpret_cast<const float4*>(B + (size_t)(kt * 16 + bRow + 8) * OUT_CH + bCol);
            *reinterpret_cast<float4*>(&Bs[bRow][bCol])     = b0;
            *reinterpret_cast<float4*>(&Bs[bRow + 8][bCol]) = b1;
        }
        __syncthreads();

        #pragma unroll
        for (int k = 0; k < 16; ++k) {
            float ra[8], rb[8];
            *reinterpret_cast<float4*>(ra)     = *reinterpret_cast<const float4*>(&As[k][ty * 8]);
            *reinterpret_cast<float4*>(ra + 4) = *reinterpret_cast<const float4*>(&As[k][ty * 8 + 4]);
            *reinterpret_cast<float4*>(rb)     = *reinterpret_cast<const float4*>(&Bs[k][tx * 8]);
            *reinterpret_cast<float4*>(rb + 4) = *reinterpret_cast<const float4*>(&Bs[k][tx * 8 + 4]);
            #pragma unroll
            for (int i = 0; i < 8; ++i)
                #pragma unroll
                for (int j = 0; j < 8; ++j)
                    acc[i][j] = fmaf(ra[i], rb[j], acc[i][j]);
        }
        __syncthreads();
    }

    // ---- store C tile ----
    #pragma unroll
    for (int i = 0; i < 8; ++i) {
        const int row = block_row + ty * 8 + i;
        if (row < M) {
            float4 v0 = make_float4(acc[i][0], acc[i][1], acc[i][2], acc[i][3]);
            float4 v1 = make_float4(acc[i][4], acc[i][5], acc[i][6], acc[i][7]);
            float* c = g_xw + (size_t)row * OUT_CH + tx * 8;
            *reinterpret_cast<float4*>(c)     = v0;
            *reinterpret_cast<float4*>(c + 4) = v1;
        }
    }
}

// ---------------------------------------------------------------------------
// out[n, :] = bias[:]   (vectorized broadcast; out has 128 cols = 32 float4)
// ---------------------------------------------------------------------------
__global__ void bias_init_kernel(float4* __restrict__ out, const float4* __restrict__ bias, int n4)
{
    int i = blockIdx.x * blockDim.x + threadIdx.x;
    if (i < n4)
        out[i] = bias[i & 31];
}

// ---------------------------------------------------------------------------
// Scatter: one warp per edge.
//   out[src] += vals[e] * xw[dst]   (128 floats, 4 per lane, red.v4.f32)
// ---------------------------------------------------------------------------
__global__ __launch_bounds__(256)
void scatter_kernel(const int* __restrict__ esrc, const int* __restrict__ edst,
                    const float* __restrict__ evals, float* __restrict__ out, int E)
{
    const int warp = (blockIdx.x * blockDim.x + threadIdx.x) >> 5;
    const int lane = threadIdx.x & 31;
    if (warp >= E) return;

    const int s   = __ldg(esrc + warp);
    const int d   = __ldg(edst + warp);
    const float v = __ldg(evals + warp);

    const float4* row = reinterpret_cast<const float4*>(g_xw + (size_t)d * OUT_CH);
    float4 m = __ldg(row + lane);
    m.x *= v; m.y *= v; m.z *= v; m.w *= v;

    float* o = out + (size_t)s * OUT_CH + lane * 4;
    asm volatile("red.global.add.v4.f32 [%0], {%1, %2, %3, %4};"
                 :: "l"(o), "f"(m.x), "f"(m.y), "f"(m.z), "f"(m.w)
                 : "memory");
}

// ---------------------------------------------------------------------------
extern "C" void kernel_launch(void* const* d_in, const int* in_sizes, int n_in,
                              void* d_out, int out_size)
{
    const float* x     = (const float*)d_in[0];   // [N, 256]
    const int*   esrc  = (const int*)  d_in[1];   // [E]
    const int*   edst  = (const int*)  d_in[2];   // [E]
    const float* evals = (const float*)d_in[3];   // [E]
    const float* W     = (const float*)d_in[4];   // [256, 128]
    const float* bias  = (const float*)d_in[5];   // [128]
    float* out = (float*)d_out;                   // [N, 128]

    const int M = in_sizes[0] / IN_CH;            // 100000
    const int E = in_sizes[1];                    // 3200000

    // 1) xw = x @ W  -> g_xw
    gemm_kernel<<<(M + 127) / 128, 256>>>(x, W, M);

    // 2) out = bias (broadcast)
    {
        int n4 = M * (OUT_CH / 4);
        bias_init_kernel<<<(n4 + 255) / 256, 256>>>(
            reinterpret_cast<float4*>(out), reinterpret_cast<const float4*>(bias), n4);
    }

    // 3) out[src] += val * xw[dst]
    {
        long long threads = (long long)E * 32;
        int blocks = (int)((threads + 255) / 256);
        scatter_kernel<<<blocks, 256>>>(esrc, edst, evals, out, E);
    }
}

// round 2
// speedup vs baseline: 1.6393x; 1.6393x over previous
#include <cuda_runtime.h>
#include <cstdint>

#define N_NODES_MAX 100000
#define E_MAX 3200000
#define IN_CH 256
#define OUT_CH 128

// ---- static device scratch (allocation-free) ----
__device__ float  g_xw[(size_t)N_NODES_MAX * OUT_CH];   // 51.2 MB
__device__ float2 g_edges[E_MAX];                        // 25.6 MB: (dst_bits, val) bucketed by src
__device__ int    g_cnt[N_NODES_MAX];                    // per-node degree
__device__ int    g_row_start[N_NODES_MAX];              // segment start in g_edges
__device__ int    g_cursor[N_NODES_MAX];                 // binning cursor
__device__ int    g_total;                               // segment allocator

// ---------------------------------------------------------------------------
// GEMM: g_xw[M,128] = A[M,256] * B[256,128], fp32 SIMT tiled (unchanged)
// ---------------------------------------------------------------------------
__global__ __launch_bounds__(256, 2)
void gemm_kernel(const float* __restrict__ A, const float* __restrict__ B, int M)
{
    __shared__ float As[16][132];
    __shared__ float Bs[16][128];

    const int tid = threadIdx.x;
    const int block_row = blockIdx.x * 128;

    const int tx = tid & 15;
    const int ty = tid >> 4;

    const int aRow = tid >> 2;
    const int aCol = (tid & 3) * 4;
    const int bRow = tid >> 5;
    const int bCol = (tid & 31) * 4;

    float acc[8][8];
    #pragma unroll
    for (int i = 0; i < 8; ++i)
        #pragma unroll
        for (int j = 0; j < 8; ++j)
            acc[i][j] = 0.0f;

    for (int kt = 0; kt < IN_CH / 16; ++kt) {
        {
            const int r0 = block_row + aRow;
            const int r1 = r0 + 64;
            float4 a0 = make_float4(0.f, 0.f, 0.f, 0.f);
            float4 a1 = a0;
            if (r0 < M)
                a0 = *reinterpret_cast<const float4*>(A + (size_t)r0 * IN_CH + kt * 16 + aCol);
            if (r1 < M)
                a1 = *reinterpret_cast<const float4*>(A + (size_t)r1 * IN_CH + kt * 16 + aCol);
            As[aCol + 0][aRow]      = a0.x;
            As[aCol + 1][aRow]      = a0.y;
            As[aCol + 2][aRow]      = a0.z;
            As[aCol + 3][aRow]      = a0.w;
            As[aCol + 0][aRow + 64] = a1.x;
            As[aCol + 1][aRow + 64] = a1.y;
            As[aCol + 2][aRow + 64] = a1.z;
            As[aCol + 3][aRow + 64] = a1.w;
        }
        {
            const float4 b0 = *reinterpret_cast<const float4*>(B + (size_t)(kt * 16 + bRow) * OUT_CH + bCol);
            const float4 b1 = *reinterpret_cast<const float4*>(B + (size_t)(kt * 16 + bRow + 8) * OUT_CH + bCol);
            *reinterpret_cast<float4*>(&Bs[bRow][bCol])     = b0;
            *reinterpret_cast<float4*>(&Bs[bRow + 8][bCol]) = b1;
        }
        __syncthreads();

        #pragma unroll
        for (int k = 0; k < 16; ++k) {
            float ra[8], rb[8];
            *reinterpret_cast<float4*>(ra)     = *reinterpret_cast<const float4*>(&As[k][ty * 8]);
            *reinterpret_cast<float4*>(ra + 4) = *reinterpret_cast<const float4*>(&As[k][ty * 8 + 4]);
            *reinterpret_cast<float4*>(rb)     = *reinterpret_cast<const float4*>(&Bs[k][tx * 8]);
            *reinterpret_cast<float4*>(rb + 4) = *reinterpret_cast<const float4*>(&Bs[k][tx * 8 + 4]);
            #pragma unroll
            for (int i = 0; i < 8; ++i)
                #pragma unroll
                for (int j = 0; j < 8; ++j)
                    acc[i][j] = fmaf(ra[i], rb[j], acc[i][j]);
        }
        __syncthreads();
    }

    #pragma unroll
    for (int i = 0; i < 8; ++i) {
        const int row = block_row + ty * 8 + i;
        if (row < M) {
            float4 v0 = make_float4(acc[i][0], acc[i][1], acc[i][2], acc[i][3]);
            float4 v1 = make_float4(acc[i][4], acc[i][5], acc[i][6], acc[i][7]);
            float* c = g_xw + (size_t)row * OUT_CH + tx * 8;
            *reinterpret_cast<float4*>(c)     = v0;
            *reinterpret_cast<float4*>(c + 4) = v1;
        }
    }
}

// ---------------------------------------------------------------------------
// CSR build phase 1: zero counters + allocator
// ---------------------------------------------------------------------------
__global__ void zero_kernel(int N)
{
    int i = blockIdx.x * blockDim.x + threadIdx.x;
    if (i < N) g_cnt[i] = 0;
    if (i == 0) g_total = 0;
}

// Phase 2: histogram over edge sources
__global__ void hist_kernel(const int* __restrict__ esrc, int E)
{
    int e = blockIdx.x * blockDim.x + threadIdx.x;
    if (e < E)
        atomicAdd(&g_cnt[esrc[e]], 1);
}

// Phase 3: segment allocation (warp-aggregated atomic; node order in the
// buffer is arbitrary — each node records its own start).
__global__ void alloc_kernel(int N)
{
    int n = blockIdx.x * blockDim.x + threadIdx.x;
    int lane = threadIdx.x & 31;
    int c = (n < N) ? g_cnt[n] : 0;

    // warp inclusive scan of c
    int scan = c;
    #pragma unroll
    for (int o = 1; o < 32; o <<= 1) {
        int t = __shfl_up_sync(0xffffffffu, scan, o);
        if (lane >= o) scan += t;
    }
    int warp_tot = __shfl_sync(0xffffffffu, scan, 31);
    int base = 0;
    if (lane == 31) base = atomicAdd(&g_total, warp_tot);
    base = __shfl_sync(0xffffffffu, base, 31);

    if (n < N) {
        int st = base + (scan - c);
        g_row_start[n] = st;
        g_cursor[n]    = st;
    }
}

// Phase 4: bin (dst, val) pairs into per-src segments
__global__ void bin_kernel(const int* __restrict__ esrc, const int* __restrict__ edst,
                           const float* __restrict__ evals, int E)
{
    int e = blockIdx.x * blockDim.x + threadIdx.x;
    if (e < E) {
        int s = esrc[e];
        int pos = atomicAdd(&g_cursor[s], 1);
        g_edges[pos] = make_float2(__int_as_float(edst[e]), evals[e]);
    }
}

// ---------------------------------------------------------------------------
// Phase 5: aggregation — one warp per node, register accumulation, one write.
//   out[n,:] = sum_e val_e * xw[dst_e, :] + bias
// ---------------------------------------------------------------------------
__global__ __launch_bounds__(256)
void aggregate_kernel(const float* __restrict__ bias, float* __restrict__ out, int N)
{
    const int node = (blockIdx.x * blockDim.x + threadIdx.x) >> 5;
    const int lane = threadIdx.x & 31;
    if (node >= N) return;

    const int start = g_row_start[node];
    const int deg   = g_cnt[node];

    float4 acc = make_float4(0.f, 0.f, 0.f, 0.f);

    for (int base = 0; base < deg; base += 32) {
        const int n = min(32, deg - base);
        float2 meta = make_float2(0.f, 0.f);
        if (lane < n)
            meta = g_edges[start + base + lane];

        #pragma unroll 4
        for (int i = 0; i < n; ++i) {
            const int   dst = __shfl_sync(0xffffffffu, __float_as_int(meta.x), i);
            const float v   = __shfl_sync(0xffffffffu, meta.y, i);
            const float4 t  = __ldg(reinterpret_cast<const float4*>(
                                        g_xw + (size_t)dst * OUT_CH) + lane);
            acc.x = fmaf(v, t.x, acc.x);
            acc.y = fmaf(v, t.y, acc.y);
            acc.z = fmaf(v, t.z, acc.z);
            acc.w = fmaf(v, t.w, acc.w);
        }
    }

    const float4 b = __ldg(reinterpret_cast<const float4*>(bias) + lane);
    acc.x += b.x; acc.y += b.y; acc.z += b.z; acc.w += b.w;

    *(reinterpret_cast<float4*>(out + (size_t)node * OUT_CH) + lane) = acc;
}

// ---------------------------------------------------------------------------
extern "C" void kernel_launch(void* const* d_in, const int* in_sizes, int n_in,
                              void* d_out, int out_size)
{
    const float* x     = (const float*)d_in[0];   // [N, 256]
    const int*   esrc  = (const int*)  d_in[1];   // [E]
    const int*   edst  = (const int*)  d_in[2];   // [E]
    const float* evals = (const float*)d_in[3];   // [E]
    const float* W     = (const float*)d_in[4];   // [256, 128]
    const float* bias  = (const float*)d_in[5];   // [128]
    float* out = (float*)d_out;                   // [N, 128]

    const int M = in_sizes[0] / IN_CH;            // 100000
    const int E = in_sizes[1];                    // 3200000

    // 1) xw = x @ W
    gemm_kernel<<<(M + 127) / 128, 256>>>(x, W, M);

    // 2) CSR build
    zero_kernel<<<(M + 255) / 256, 256>>>(M);
    hist_kernel<<<(E + 255) / 256, 256>>>(esrc, E);
    alloc_kernel<<<(M + 255) / 256, 256>>>(M);
    bin_kernel<<<(E + 255) / 256, 256>>>(esrc, edst, evals, E);

    // 3) aggregate + bias, one warp per node
    {
        long long threads = (long long)M * 32;
        int blocks = (int)((threads + 255) / 256);
        aggregate_kernel<<<blocks, 256>>>(bias, out, M);
    }
}

// round 3
// speedup vs baseline: 1.6914x; 1.0318x over previous
#include <cuda_runtime.h>
#include <cuda_fp16.h>
#include <cstdint>

#define N_NODES_MAX 100000
#define E_MAX 3200000
#define IN_CH 256
#define OUT_CH 128

// ---- static device scratch (allocation-free) ----
__device__ __half  g_xw_h[(size_t)N_NODES_MAX * OUT_CH];  // 25.6 MB, fp16 xw
__device__ float2  g_edges[E_MAX];                         // (dst_bits, val) bucketed by src
__device__ int     g_cnt[N_NODES_MAX];
__device__ int     g_row_start[N_NODES_MAX];
__device__ int     g_cursor[N_NODES_MAX];
__device__ int     g_total;

// ---------------------------------------------------------------------------
// tf32 helpers
// ---------------------------------------------------------------------------
__device__ __forceinline__ unsigned f2tf32(float x) {
    unsigned r;
    asm("cvt.rna.tf32.f32 %0, %1;" : "=r"(r) : "f"(x));
    return r;
}

__device__ __forceinline__ void mma_tf32(float& c0, float& c1, float& c2, float& c3,
                                         unsigned a0, unsigned a1, unsigned a2, unsigned a3,
                                         unsigned b0, unsigned b1)
{
    asm volatile(
        "mma.sync.aligned.m16n8k8.row.col.f32.tf32.tf32.f32 "
        "{%0,%1,%2,%3}, {%4,%5,%6,%7}, {%8,%9}, {%0,%1,%2,%3};"
        : "+f"(c0), "+f"(c1), "+f"(c2), "+f"(c3)
        : "r"(a0), "r"(a1), "r"(a2), "r"(a3), "r"(b0), "r"(b1));
}

// ---------------------------------------------------------------------------
// GEMM: g_xw_h[M,128] = fp16( A[M,256] * B[256,128] ), tf32x3 tensor cores
// CTA tile 128(M) x 128(N), k-chunk 16, 256 threads = 8 warps in 2x4 grid,
// warp tile 64x32 (m-tiles=4, n-tiles=4).
// ---------------------------------------------------------------------------
__global__ __launch_bounds__(256)
void gemm_tf32_kernel(const float* __restrict__ A, const float* __restrict__ B, int M)
{
    __shared__ unsigned Ahi[16][136];
    __shared__ unsigned Alo[16][136];
    __shared__ unsigned Bhi[16][136];
    __shared__ unsigned Blo[16][136];

    const int tid  = threadIdx.x;
    const int lane = tid & 31;
    const int warp = tid >> 5;
    const int brow = blockIdx.x * 128;

    const int wm = warp >> 2;        // 0..1 -> m base = wm*64
    const int wn = warp & 3;         // 0..3 -> n base = wn*32
    const int mbase = wm * 64;
    const int nbase = wn * 32;

    // A tile global-load mapping: 128 rows x 16 k, 8 floats/thread
    const int aRow  = tid >> 1;          // 0..127
    const int aKoff = (tid & 1) * 8;     // 0 or 8
    // B tile: 16 k-rows x 128 n, 8 floats/thread
    const int bK    = tid >> 4;          // 0..15
    const int bN    = (tid & 15) * 8;    // 0..120

    float acc[4][4][4];                  // [mt][nt][frag]
    #pragma unroll
    for (int mt = 0; mt < 4; ++mt)
        #pragma unroll
        for (int nt = 0; nt < 4; ++nt)
            #pragma unroll
            for (int f = 0; f < 4; ++f)
                acc[mt][nt][f] = 0.0f;

    for (int kt = 0; kt < IN_CH / 16; ++kt) {
        // ---- load + split A tile ----
        {
            const int r = brow + aRow;
            float4 v0 = make_float4(0.f, 0.f, 0.f, 0.f), v1 = v0;
            if (r < M) {
                const float* p = A + (size_t)r * IN_CH + kt * 16 + aKoff;
                v0 = *reinterpret_cast<const float4*>(p);
                v1 = *reinterpret_cast<const float4*>(p + 4);
            }
            float va[8] = {v0.x, v0.y, v0.z, v0.w, v1.x, v1.y, v1.z, v1.w};
            #pragma unroll
            for (int i = 0; i < 8; ++i) {
                unsigned hb = f2tf32(va[i]);
                float lo = va[i] - __uint_as_float(hb);
                Ahi[aKoff + i][aRow] = hb;
                Alo[aKoff + i][aRow] = f2tf32(lo);
            }
        }
        // ---- load + split B tile ----
        {
            const float* p = B + (size_t)(kt * 16 + bK) * OUT_CH + bN;
            float4 v0 = *reinterpret_cast<const float4*>(p);
            float4 v1 = *reinterpret_cast<const float4*>(p + 4);
            float vb[8] = {v0.x, v0.y, v0.z, v0.w, v1.x, v1.y, v1.z, v1.w};
            #pragma unroll
            for (int i = 0; i < 8; ++i) {
                unsigned hb = f2tf32(vb[i]);
                float lo = vb[i] - __uint_as_float(hb);
                Bhi[bK][bN + i] = hb;
                Blo[bK][bN + i] = f2tf32(lo);
            }
        }
        __syncthreads();

        #pragma unroll
        for (int ks = 0; ks < 2; ++ks) {
            const int k0 = ks * 8 + (lane & 3);
            const int r0 = lane >> 2;

            unsigned ah[4][4], al[4][4];
            #pragma unroll
            for (int mt = 0; mt < 4; ++mt) {
                const int m0 = mbase + mt * 16 + r0;
                ah[mt][0] = Ahi[k0][m0];
                ah[mt][1] = Ahi[k0][m0 + 8];
                ah[mt][2] = Ahi[k0 + 4][m0];
                ah[mt][3] = Ahi[k0 + 4][m0 + 8];
                al[mt][0] = Alo[k0][m0];
                al[mt][1] = Alo[k0][m0 + 8];
                al[mt][2] = Alo[k0 + 4][m0];
                al[mt][3] = Alo[k0 + 4][m0 + 8];
            }
            unsigned bh[4][2], bl[4][2];
            #pragma unroll
            for (int nt = 0; nt < 4; ++nt) {
                const int n0 = nbase + nt * 8 + r0;
                bh[nt][0] = Bhi[k0][n0];
                bh[nt][1] = Bhi[k0 + 4][n0];
                bl[nt][0] = Blo[k0][n0];
                bl[nt][1] = Blo[k0 + 4][n0];
            }

            #pragma unroll
            for (int mt = 0; mt < 4; ++mt)
                #pragma unroll
                for (int nt = 0; nt < 4; ++nt) {
                    float* c = acc[mt][nt];
                    mma_tf32(c[0], c[1], c[2], c[3],
                             ah[mt][0], ah[mt][1], ah[mt][2], ah[mt][3],
                             bh[nt][0], bh[nt][1]);
                    mma_tf32(c[0], c[1], c[2], c[3],
                             ah[mt][0], ah[mt][1], ah[mt][2], ah[mt][3],
                             bl[nt][0], bl[nt][1]);
                    mma_tf32(c[0], c[1], c[2], c[3],
                             al[mt][0], al[mt][1], al[mt][2], al[mt][3],
                             bh[nt][0], bh[nt][1]);
                }
        }
        __syncthreads();
    }

    // ---- epilogue: fp16 store ----
    const int crow = lane >> 2;
    const int ccol = (lane & 3) * 2;
    #pragma unroll
    for (int mt = 0; mt < 4; ++mt) {
        #pragma unroll
        for (int nt = 0; nt < 4; ++nt) {
            const int col = nbase + nt * 8 + ccol;
            const int r0 = brow + mbase + mt * 16 + crow;
            const int r1 = r0 + 8;
            if (r0 < M)
                *reinterpret_cast<__half2*>(g_xw_h + (size_t)r0 * OUT_CH + col) =
                    __floats2half2_rn(acc[mt][nt][0], acc[mt][nt][1]);
            if (r1 < M)
                *reinterpret_cast<__half2*>(g_xw_h + (size_t)r1 * OUT_CH + col) =
                    __floats2half2_rn(acc[mt][nt][2], acc[mt][nt][3]);
        }
    }
}

// ---------------------------------------------------------------------------
// CSR build (unchanged)
// ---------------------------------------------------------------------------
__global__ void zero_kernel(int N)
{
    int i = blockIdx.x * blockDim.x + threadIdx.x;
    if (i < N) g_cnt[i] = 0;
    if (i == 0) g_total = 0;
}

__global__ void hist_kernel(const int* __restrict__ esrc, int E)
{
    int e = blockIdx.x * blockDim.x + threadIdx.x;
    if (e < E)
        atomicAdd(&g_cnt[esrc[e]], 1);
}

__global__ void alloc_kernel(int N)
{
    int n = blockIdx.x * blockDim.x + threadIdx.x;
    int lane = threadIdx.x & 31;
    int c = (n < N) ? g_cnt[n] : 0;

    int scan = c;
    #pragma unroll
    for (int o = 1; o < 32; o <<= 1) {
        int t = __shfl_up_sync(0xffffffffu, scan, o);
        if (lane >= o) scan += t;
    }
    int warp_tot = __shfl_sync(0xffffffffu, scan, 31);
    int base = 0;
    if (lane == 31) base = atomicAdd(&g_total, warp_tot);
    base = __shfl_sync(0xffffffffu, base, 31);

    if (n < N) {
        int st = base + (scan - c);
        g_row_start[n] = st;
        g_cursor[n]    = st;
    }
}

__global__ void bin_kernel(const int* __restrict__ esrc, const int* __restrict__ edst,
                           const float* __restrict__ evals, int E)
{
    int e = blockIdx.x * blockDim.x + threadIdx.x;
    if (e < E) {
        int s = esrc[e];
        int pos = atomicAdd(&g_cursor[s], 1);
        g_edges[pos] = make_float2(__int_as_float(edst[e]), evals[e]);
    }
}

// ---------------------------------------------------------------------------
// Aggregation: one warp per node, fp16 gathers (8B/lane), fp32 accumulators.
// ---------------------------------------------------------------------------
__global__ __launch_bounds__(256)
void aggregate_kernel(const float* __restrict__ bias, float* __restrict__ out, int N)
{
    const int node = (blockIdx.x * blockDim.x + threadIdx.x) >> 5;
    const int lane = threadIdx.x & 31;
    if (node >= N) return;

    const int start = g_row_start[node];
    const int deg   = g_cnt[node];

    float4 acc = make_float4(0.f, 0.f, 0.f, 0.f);

    for (int base = 0; base < deg; base += 32) {
        const int n = min(32, deg - base);
        float2 meta = make_float2(0.f, 0.f);
        if (lane < n)
            meta = g_edges[start + base + lane];

        #pragma unroll 4
        for (int i = 0; i < n; ++i) {
            const int   dst = __shfl_sync(0xffffffffu, __float_as_int(meta.x), i);
            const float v   = __shfl_sync(0xffffffffu, meta.y, i);

            const uint2 raw = __ldg(reinterpret_cast<const uint2*>(
                                        g_xw_h + (size_t)dst * OUT_CH) + lane);
            const __half2 h0 = *reinterpret_cast<const __half2*>(&raw.x);
            const __half2 h1 = *reinterpret_cast<const __half2*>(&raw.y);
            const float2 f0 = __half22float2(h0);
            const float2 f1 = __half22float2(h1);

            acc.x = fmaf(v, f0.x, acc.x);
            acc.y = fmaf(v, f0.y, acc.y);
            acc.z = fmaf(v, f1.x, acc.z);
            acc.w = fmaf(v, f1.y, acc.w);
        }
    }

    const float4 b = __ldg(reinterpret_cast<const float4*>(bias) + lane);
    acc.x += b.x; acc.y += b.y; acc.z += b.z; acc.w += b.w;

    *(reinterpret_cast<float4*>(out + (size_t)node * OUT_CH) + lane) = acc;
}

// ---------------------------------------------------------------------------
extern "C" void kernel_launch(void* const* d_in, const int* in_sizes, int n_in,
                              void* d_out, int out_size)
{
    const float* x     = (const float*)d_in[0];   // [N, 256]
    const int*   esrc  = (const int*)  d_in[1];   // [E]
    const int*   edst  = (const int*)  d_in[2];   // [E]
    const float* evals = (const float*)d_in[3];   // [E]
    const float* W     = (const float*)d_in[4];   // [256, 128]
    const float* bias  = (const float*)d_in[5];   // [128]
    float* out = (float*)d_out;                   // [N, 128]

    const int M = in_sizes[0] / IN_CH;            // 100000
    const int E = in_sizes[1];                    // 3200000

    // 1) xw = fp16(x @ W)  (tf32x3 tensor cores)
    gemm_tf32_kernel<<<(M + 127) / 128, 256>>>(x, W, M);

    // 2) CSR build
    zero_kernel<<<(M + 255) / 256, 256>>>(M);
    hist_kernel<<<(E + 255) / 256, 256>>>(esrc, E);
    alloc_kernel<<<(M + 255) / 256, 256>>>(M);
    bin_kernel<<<(E + 255) / 256, 256>>>(esrc, edst, evals, E);

    // 3) aggregate + bias
    {
        long long threads = (long long)M * 32;
        int blocks = (int)((threads + 255) / 256);
        aggregate_kernel<<<blocks, 256>>>(bias, out, M);
    }
}

// round 4
// speedup vs baseline: 2.6976x; 1.5949x over previous
#include <cuda_runtime.h>
#include <cuda_fp16.h>
#include <cstdint>

#define N_NODES_MAX 100000
#define E_MAX 3200000
#define IN_CH 256
#define OUT_CH 128
#define AS_STRIDE 40   // halves per smem row (32 data + 8 pad)

// ---- static device scratch (allocation-free) ----
__device__ __half  g_xw_h[(size_t)N_NODES_MAX * OUT_CH];  // 25.6 MB fp16 xw
__device__ __half  g_wt[(size_t)OUT_CH * IN_CH];           // W^T fp16 [n][k], 64 KB
__device__ float2  g_edges[E_MAX];                          // (dst_bits, val) bucketed by src
__device__ int     g_cnt[N_NODES_MAX];
__device__ int     g_row_start[N_NODES_MAX];
__device__ int     g_cursor[N_NODES_MAX];
__device__ int     g_total;

__device__ __forceinline__ unsigned pack_h2(float a, float b) {
    __half2 h = __floats2half2_rn(a, b);
    return *reinterpret_cast<unsigned*>(&h);
}

// ---------------------------------------------------------------------------
// W [256,128] fp32 -> g_wt [128][256] fp16 (transposed)
// ---------------------------------------------------------------------------
__global__ void convert_w_kernel(const float* __restrict__ W)
{
    int idx = blockIdx.x * blockDim.x + threadIdx.x;
    if (idx < IN_CH * OUT_CH) {
        int k = idx >> 7;        // row in W
        int n = idx & 127;       // col in W
        g_wt[(size_t)n * IN_CH + k] = __float2half_rn(W[idx]);
    }
}

// ---------------------------------------------------------------------------
// GEMM: g_xw_h[M,128] = fp16( A[M,256] * W[256,128] ) via fp16 HMMA m16n8k16.
// CTA tile 128(M) x 128(N), K-tile 32, double-buffered smem, 256 threads.
// Warp grid 2(M) x 4(N): warp tile 64x32 -> mtiles=4, ntiles=4.
// ---------------------------------------------------------------------------
__global__ __launch_bounds__(256, 2)
void gemm_f16_kernel(const float* __restrict__ A, int M)
{
    __shared__ __half As[2][128 * AS_STRIDE];
    __shared__ __half Bs[2][128 * AS_STRIDE];

    const int tid  = threadIdx.x;
    const int lane = tid & 31;
    const int warp = tid >> 5;
    const int brow = blockIdx.x * 128;

    const int wm = warp >> 2;       // 0..1  -> m base = wm*64
    const int wn = warp & 3;        // 0..3  -> n base = wn*32
    const int g  = lane >> 2;       // 0..7
    const int t  = lane & 3;        // 0..3

    // tile-load mapping: 128 rows x 32 k, 16 elements (halves/floats) per thread
    const int lrow = tid >> 1;            // 0..127
    const int lkh  = (tid & 1) * 16;      // 0 or 16

    float acc[4][4][4];
    #pragma unroll
    for (int mt = 0; mt < 4; ++mt)
        #pragma unroll
        for (int nt = 0; nt < 4; ++nt)
            #pragma unroll
            for (int f = 0; f < 4; ++f)
                acc[mt][nt][f] = 0.0f;

    float4 sa[4];
    uint4  sb[2];

    // ---- prologue: load tile 0 ----
    {
        const int gr = brow + lrow;
        if (gr < M) {
            const float* pa = A + (size_t)gr * IN_CH + lkh;
            sa[0] = *reinterpret_cast<const float4*>(pa);
            sa[1] = *reinterpret_cast<const float4*>(pa + 4);
            sa[2] = *reinterpret_cast<const float4*>(pa + 8);
            sa[3] = *reinterpret_cast<const float4*>(pa + 12);
        } else {
            sa[0] = sa[1] = sa[2] = sa[3] = make_float4(0.f, 0.f, 0.f, 0.f);
        }
        const uint4* pb = reinterpret_cast<const uint4*>(g_wt + (size_t)lrow * IN_CH + lkh);
        sb[0] = pb[0];
        sb[1] = pb[1];
    }
    // store stage 0
    {
        uint4 u0, u1;
        u0.x = pack_h2(sa[0].x, sa[0].y); u0.y = pack_h2(sa[0].z, sa[0].w);
        u0.z = pack_h2(sa[1].x, sa[1].y); u0.w = pack_h2(sa[1].z, sa[1].w);
        u1.x = pack_h2(sa[2].x, sa[2].y); u1.y = pack_h2(sa[2].z, sa[2].w);
        u1.z = pack_h2(sa[3].x, sa[3].y); u1.w = pack_h2(sa[3].z, sa[3].w);
        uint4* da = reinterpret_cast<uint4*>(&As[0][lrow * AS_STRIDE + lkh]);
        da[0] = u0; da[1] = u1;
        uint4* db = reinterpret_cast<uint4*>(&Bs[0][lrow * AS_STRIDE + lkh]);
        db[0] = sb[0]; db[1] = sb[1];
    }
    __syncthreads();

    for (int kt = 0; kt < IN_CH / 32; ++kt) {
        // ---- prefetch next tile into regs ----
        if (kt < IN_CH / 32 - 1) {
            const int gr = brow + lrow;
            if (gr < M) {
                const float* pa = A + (size_t)gr * IN_CH + (kt + 1) * 32 + lkh;
                sa[0] = *reinterpret_cast<const float4*>(pa);
                sa[1] = *reinterpret_cast<const float4*>(pa + 4);
                sa[2] = *reinterpret_cast<const float4*>(pa + 8);
                sa[3] = *reinterpret_cast<const float4*>(pa + 12);
            } else {
                sa[0] = sa[1] = sa[2] = sa[3] = make_float4(0.f, 0.f, 0.f, 0.f);
            }
            const uint4* pb = reinterpret_cast<const uint4*>(
                g_wt + (size_t)lrow * IN_CH + (kt + 1) * 32 + lkh);
            sb[0] = pb[0];
            sb[1] = pb[1];
        }

        // ---- compute on stage kt&1 ----
        const int st = kt & 1;
        #pragma unroll
        for (int s = 0; s < 2; ++s) {
            const int k0 = s * 16;

            unsigned a[4][4];
            #pragma unroll
            for (int mt = 0; mt < 4; ++mt) {
                const __half* pm = &As[st][(wm * 64 + mt * 16 + g) * AS_STRIDE + k0 + t * 2];
                a[mt][0] = *reinterpret_cast<const unsigned*>(pm);
                a[mt][1] = *reinterpret_cast<const unsigned*>(pm + 8 * AS_STRIDE);
                a[mt][2] = *reinterpret_cast<const unsigned*>(pm + 8);
                a[mt][3] = *reinterpret_cast<const unsigned*>(pm + 8 * AS_STRIDE + 8);
            }
            unsigned b[4][2];
            #pragma unroll
            for (int nt = 0; nt < 4; ++nt) {
                const __half* pn = &Bs[st][(wn * 32 + nt * 8 + g) * AS_STRIDE + k0 + t * 2];
                b[nt][0] = *reinterpret_cast<const unsigned*>(pn);
                b[nt][1] = *reinterpret_cast<const unsigned*>(pn + 8);
            }

            #pragma unroll
            for (int mt = 0; mt < 4; ++mt)
                #pragma unroll
                for (int nt = 0; nt < 4; ++nt) {
                    float* c = acc[mt][nt];
                    asm volatile(
                        "mma.sync.aligned.m16n8k16.row.col.f32.f16.f16.f32 "
                        "{%0,%1,%2,%3}, {%4,%5,%6,%7}, {%8,%9}, {%0,%1,%2,%3};"
                        : "+f"(c[0]), "+f"(c[1]), "+f"(c[2]), "+f"(c[3])
                        : "r"(a[mt][0]), "r"(a[mt][1]), "r"(a[mt][2]), "r"(a[mt][3]),
                          "r"(b[nt][0]), "r"(b[nt][1]));
                }
        }

        // ---- store prefetched tile into the other stage ----
        if (kt < IN_CH / 32 - 1) {
            const int ns = (kt + 1) & 1;
            uint4 u0, u1;
            u0.x = pack_h2(sa[0].x, sa[0].y); u0.y = pack_h2(sa[0].z, sa[0].w);
            u0.z = pack_h2(sa[1].x, sa[1].y); u0.w = pack_h2(sa[1].z, sa[1].w);
            u1.x = pack_h2(sa[2].x, sa[2].y); u1.y = pack_h2(sa[2].z, sa[2].w);
            u1.z = pack_h2(sa[3].x, sa[3].y); u1.w = pack_h2(sa[3].z, sa[3].w);
            uint4* da = reinterpret_cast<uint4*>(&As[ns][lrow * AS_STRIDE + lkh]);
            da[0] = u0; da[1] = u1;
            uint4* db = reinterpret_cast<uint4*>(&Bs[ns][lrow * AS_STRIDE + lkh]);
            db[0] = sb[0]; db[1] = sb[1];
            __syncthreads();
        }
    }

    // ---- epilogue: fp16 store ----
    #pragma unroll
    for (int mt = 0; mt < 4; ++mt) {
        #pragma unroll
        for (int nt = 0; nt < 4; ++nt) {
            const int col = wn * 32 + nt * 8 + t * 2;
            const int r0  = brow + wm * 64 + mt * 16 + g;
            const int r1  = r0 + 8;
            if (r0 < M) {
                unsigned p = pack_h2(acc[mt][nt][0], acc[mt][nt][1]);
                *reinterpret_cast<unsigned*>(g_xw_h + (size_t)r0 * OUT_CH + col) = p;
            }
            if (r1 < M) {
                unsigned p = pack_h2(acc[mt][nt][2], acc[mt][nt][3]);
                *reinterpret_cast<unsigned*>(g_xw_h + (size_t)r1 * OUT_CH + col) = p;
            }
        }
    }
}

// ---------------------------------------------------------------------------
// CSR build
// ---------------------------------------------------------------------------
__global__ void zero_kernel(int N)
{
    int i = blockIdx.x * blockDim.x + threadIdx.x;
    if (i < N) g_cnt[i] = 0;
    if (i == 0) g_total = 0;
}

__global__ void hist_kernel(const int* __restrict__ esrc, int E)
{
    int e = blockIdx.x * blockDim.x + threadIdx.x;
    if (e < E)
        atomicAdd(&g_cnt[esrc[e]], 1);
}

__global__ void alloc_kernel(int N)
{
    int n = blockIdx.x * blockDim.x + threadIdx.x;
    int lane = threadIdx.x & 31;
    int c = (n < N) ? g_cnt[n] : 0;

    int scan = c;
    #pragma unroll
    for (int o = 1; o < 32; o <<= 1) {
        int t = __shfl_up_sync(0xffffffffu, scan, o);
        if (lane >= o) scan += t;
    }
    int warp_tot = __shfl_sync(0xffffffffu, scan, 31);
    int base = 0;
    if (lane == 31) base = atomicAdd(&g_total, warp_tot);
    base = __shfl_sync(0xffffffffu, base, 31);

    if (n < N) {
        int st = base + (scan - c);
        g_row_start[n] = st;
        g_cursor[n]    = st;
    }
}

__global__ void bin_kernel(const int* __restrict__ esrc, const int* __restrict__ edst,
                           const float* __restrict__ evals, int E)
{
    int e = blockIdx.x * blockDim.x + threadIdx.x;
    if (e < E) {
        int s = esrc[e];
        int pos = atomicAdd(&g_cursor[s], 1);
        g_edges[pos] = make_float2(__int_as_float(edst[e]), evals[e]);
    }
}

// ---------------------------------------------------------------------------
// Aggregation: one warp per node, fp16 gathers, fp32 accumulators.
// ---------------------------------------------------------------------------
__global__ __launch_bounds__(256)
void aggregate_kernel(const float* __restrict__ bias, float* __restrict__ out, int N)
{
    const int node = (blockIdx.x * blockDim.x + threadIdx.x) >> 5;
    const int lane = threadIdx.x & 31;
    if (node >= N) return;

    const int start = g_row_start[node];
    const int deg   = g_cnt[node];

    float4 acc = make_float4(0.f, 0.f, 0.f, 0.f);

    for (int base = 0; base < deg; base += 32) {
        const int n = min(32, deg - base);
        float2 meta = make_float2(0.f, 0.f);
        if (lane < n)
            meta = g_edges[start + base + lane];

        #pragma unroll 4
        for (int i = 0; i < n; ++i) {
            const int   dst = __shfl_sync(0xffffffffu, __float_as_int(meta.x), i);
            const float v   = __shfl_sync(0xffffffffu, meta.y, i);

            const uint2 raw = __ldg(reinterpret_cast<const uint2*>(
                                        g_xw_h + (size_t)dst * OUT_CH) + lane);
            const __half2 h0 = *reinterpret_cast<const __half2*>(&raw.x);
            const __half2 h1 = *reinterpret_cast<const __half2*>(&raw.y);
            const float2 f0 = __half22float2(h0);
            const float2 f1 = __half22float2(h1);

            acc.x = fmaf(v, f0.x, acc.x);
            acc.y = fmaf(v, f0.y, acc.y);
            acc.z = fmaf(v, f1.x, acc.z);
            acc.w = fmaf(v, f1.y, acc.w);
        }
    }

    const float4 b = __ldg(reinterpret_cast<const float4*>(bias) + lane);
    acc.x += b.x; acc.y += b.y; acc.z += b.z; acc.w += b.w;

    *(reinterpret_cast<float4*>(out + (size_t)node * OUT_CH) + lane) = acc;
}

// ---------------------------------------------------------------------------
extern "C" void kernel_launch(void* const* d_in, const int* in_sizes, int n_in,
                              void* d_out, int out_size)
{
    const float* x     = (const float*)d_in[0];   // [N, 256]
    const int*   esrc  = (const int*)  d_in[1];   // [E]
    const int*   edst  = (const int*)  d_in[2];   // [E]
    const float* evals = (const float*)d_in[3];   // [E]
    const float* W     = (const float*)d_in[4];   // [256, 128]
    const float* bias  = (const float*)d_in[5];   // [128]
    float* out = (float*)d_out;                   // [N, 128]

    const int M = in_sizes[0] / IN_CH;            // 100000
    const int E = in_sizes[1];                    // 3200000

    // 1) W -> W^T fp16
    convert_w_kernel<<<(IN_CH * OUT_CH + 255) / 256, 256>>>(W);

    // 2) xw = fp16(x @ W)  (fp16 HMMA)
    gemm_f16_kernel<<<(M + 127) / 128, 256>>>(x, M);

    // 3) CSR build
    zero_kernel<<<(M + 255) / 256, 256>>>(M);
    hist_kernel<<<(E + 255) / 256, 256>>>(esrc, E);
    alloc_kernel<<<(M + 255) / 256, 256>>>(M);
    bin_kernel<<<(E + 255) / 256, 256>>>(esrc, edst, evals, E);

    // 4) aggregate + bias
    {
        long long threads = (long long)M * 32;
        int blocks = (int)((threads + 255) / 256);
        aggregate_kernel<<<blocks, 256>>>(bias, out, M);
    }
}

// round 5
// speedup vs baseline: 2.8371x; 1.0517x over previous
#include <cuda_runtime.h>
#include <cuda_fp16.h>
#include <cstdint>

#define N_NODES_MAX 100000
#define E_MAX 3200000
#define IN_CH 256
#define OUT_CH 128
#define NT (IN_CH / 32)   // 8 k-tiles

// ---- static device scratch (allocation-free) ----
__device__ __half  g_xw_h[(size_t)N_NODES_MAX * OUT_CH];  // 25.6 MB fp16 xw
__device__ __half  g_wt[(size_t)OUT_CH * IN_CH];           // W^T fp16 [n][k]
__device__ float2  g_edges[E_MAX];                          // (dst_bits, val) bucketed by src
__device__ int     g_cnt[N_NODES_MAX];                      // zero on entry (restored by aggregate)
__device__ int     g_row_start[N_NODES_MAX];
__device__ int     g_cursor[N_NODES_MAX];
__device__ int     g_total;                                 // zero on entry (restored by aggregate)

// ---- host-side streams/events for fork-join capture (infra, created once) ----
struct HxStreams {
    cudaStream_t s2;
    cudaEvent_t  e1, e2;
    HxStreams() {
        cudaStreamCreateWithFlags(&s2, cudaStreamNonBlocking);
        cudaEventCreateWithFlags(&e1, cudaEventDisableTiming);
        cudaEventCreateWithFlags(&e2, cudaEventDisableTiming);
    }
};
static HxStreams g_hx;

__device__ __forceinline__ unsigned pack_h2(float a, float b) {
    __half2 h = __floats2half2_rn(a, b);
    return *reinterpret_cast<unsigned*>(&h);
}

// ---------------------------------------------------------------------------
// W [256,128] fp32 -> g_wt [128][256] fp16 (transposed)
// ---------------------------------------------------------------------------
__global__ void convert_w_kernel(const float* __restrict__ W)
{
    int idx = blockIdx.x * blockDim.x + threadIdx.x;
    if (idx < IN_CH * OUT_CH) {
        int k = idx >> 7;
        int n = idx & 127;
        g_wt[(size_t)n * IN_CH + k] = __float2half_rn(W[idx]);
    }
}

// ---------------------------------------------------------------------------
// GEMM: g_xw_h[M,128] = fp16( A[M,256] * W ), fp16 HMMA m16n8k16.
// cp.async pipeline: A kept fp32 in smem (swizzled 16B chunks), converted to
// fp16 at fragment-read time. B fp16 from g_wt (swizzled). 2-stage double buf.
// CTA 128x128, ktile 32, 256 thr, warp grid 2x4 (warp tile 64x32).
// ---------------------------------------------------------------------------
__global__ __launch_bounds__(256, 2)
void gemm_f16_kernel(const float* __restrict__ A, int M)
{
    __shared__ float  As[2][128 * 32];   // 32 KB, swizzle: chunk c at (c ^ (row&7))
    __shared__ __half Bs[2][128 * 32];   // 16 KB, swizzle: chunk c at (c ^ ((row>>1)&3))

    const int tid  = threadIdx.x;
    const int lane = tid & 31;
    const int warp = tid >> 5;
    const int brow = blockIdx.x * 128;

    const int wm = warp >> 2;        // 0..1
    const int wn = warp & 3;         // 0..3
    const int g  = lane >> 2;        // 0..7
    const int t  = lane & 3;         // 0..3

    // ---- cp.async load mapping ----
    const int arow = tid >> 1;              // 0..127
    const int ac0  = (tid & 1) * 4;         // chunk base (4 chunks of 16B per thread)
    const bool avalid = (brow + arow) < M;
    const float* asrc = A + (size_t)(brow + arow) * IN_CH + ac0 * 4;

    const int brw = tid >> 1;               // 0..127 (B row = n)
    const int bc0 = (tid & 1) * 2;          // 2 chunks of 16B per thread
    const __half* bsrc = g_wt + (size_t)brw * IN_CH + bc0 * 8;

    const uint32_t a_base = (uint32_t)__cvta_generic_to_shared(&As[0][0]);
    const uint32_t b_base = (uint32_t)__cvta_generic_to_shared(&Bs[0][0]);
    uint32_t a_dst[4], b_dst[2];
    #pragma unroll
    for (int j = 0; j < 4; ++j) {
        const int c = ac0 + j;
        a_dst[j] = a_base + (uint32_t)(arow * 32 + ((c ^ (arow & 7)) * 4)) * 4u;
    }
    #pragma unroll
    for (int j = 0; j < 2; ++j) {
        const int c = bc0 + j;
        b_dst[j] = b_base + (uint32_t)(brw * 32 + ((c ^ ((brw >> 1) & 3)) * 8)) * 2u;
    }

    auto issue = [&](int kt, int s) {
        const float* ap = asrc + kt * 32;
        const int asz = avalid ? 16 : 0;
        #pragma unroll
        for (int j = 0; j < 4; ++j)
            asm volatile("cp.async.cg.shared.global [%0], [%1], 16, %2;"
                         :: "r"(a_dst[j] + s * 16384), "l"(ap + j * 4), "r"(asz) : "memory");
        const __half* bp = bsrc + kt * 32;
        #pragma unroll
        for (int j = 0; j < 2; ++j)
            asm volatile("cp.async.cg.shared.global [%0], [%1], 16;"
                         :: "r"(b_dst[j] + s * 8192), "l"(bp + j * 8) : "memory");
        asm volatile("cp.async.commit_group;" ::: "memory");
    };

    float acc[4][4][4];
    #pragma unroll
    for (int mt = 0; mt < 4; ++mt)
        #pragma unroll
        for (int nt = 0; nt < 4; ++nt)
            #pragma unroll
            for (int f = 0; f < 4; ++f)
                acc[mt][nt][f] = 0.0f;

    issue(0, 0);

    const int o  = (t * 2) & 3;   // float offset within A chunk
    const int bo = t * 2;         // half offset within B chunk
    const int bswz = (g >> 1) & 3;

    #pragma unroll
    for (int kt = 0; kt < NT; ++kt) {
        asm volatile("cp.async.wait_group 0;" ::: "memory");
        __syncthreads();
        if (kt + 1 < NT) issue(kt + 1, (kt + 1) & 1);

        const int st = kt & 1;
        const float*  Ast = As[st];
        const __half* Bst = Bs[st];

        #pragma unroll
        for (int s = 0; s < 2; ++s) {
            const int c0 = s * 4 + (t >> 1);   // A chunk for k = s*16 + 2t
            const int cb = s * 2;              // B chunk for k = s*16 + 2t

            unsigned a[4][4];
            #pragma unroll
            for (int mt = 0; mt < 4; ++mt) {
                const int r0 = wm * 64 + mt * 16 + g;
                const float2 f00 = *reinterpret_cast<const float2*>(
                    &Ast[r0 * 32       + (((c0    ) ^ g) << 2) + o]);
                const float2 f01 = *reinterpret_cast<const float2*>(
                    &Ast[(r0 + 8) * 32 + (((c0    ) ^ g) << 2) + o]);
                const float2 f10 = *reinterpret_cast<const float2*>(
                    &Ast[r0 * 32       + (((c0 + 2) ^ g) << 2) + o]);
                const float2 f11 = *reinterpret_cast<const float2*>(
                    &Ast[(r0 + 8) * 32 + (((c0 + 2) ^ g) << 2) + o]);
                a[mt][0] = pack_h2(f00.x, f00.y);
                a[mt][1] = pack_h2(f01.x, f01.y);
                a[mt][2] = pack_h2(f10.x, f10.y);
                a[mt][3] = pack_h2(f11.x, f11.y);
            }
            unsigned b[4][2];
            #pragma unroll
            for (int nt = 0; nt < 4; ++nt) {
                const int n = wn * 32 + nt * 8 + g;
                b[nt][0] = *reinterpret_cast<const unsigned*>(
                    &Bst[n * 32 + (((cb    ) ^ bswz) << 3) + bo]);
                b[nt][1] = *reinterpret_cast<const unsigned*>(
                    &Bst[n * 32 + (((cb + 1) ^ bswz) << 3) + bo]);
            }

            #pragma unroll
            for (int mt = 0; mt < 4; ++mt)
                #pragma unroll
                for (int nt = 0; nt < 4; ++nt) {
                    float* c = acc[mt][nt];
                    asm volatile(
                        "mma.sync.aligned.m16n8k16.row.col.f32.f16.f16.f32 "
                        "{%0,%1,%2,%3}, {%4,%5,%6,%7}, {%8,%9}, {%0,%1,%2,%3};"
                        : "+f"(c[0]), "+f"(c[1]), "+f"(c[2]), "+f"(c[3])
                        : "r"(a[mt][0]), "r"(a[mt][1]), "r"(a[mt][2]), "r"(a[mt][3]),
                          "r"(b[nt][0]), "r"(b[nt][1]));
                }
        }
        __syncthreads();
    }

    // ---- epilogue: fp16 store ----
    #pragma unroll
    for (int mt = 0; mt < 4; ++mt) {
        #pragma unroll
        for (int nt = 0; nt < 4; ++nt) {
            const int col = wn * 32 + nt * 8 + t * 2;
            const int r0  = brow + wm * 64 + mt * 16 + g;
            const int r1  = r0 + 8;
            if (r0 < M)
                *reinterpret_cast<unsigned*>(g_xw_h + (size_t)r0 * OUT_CH + col) =
                    pack_h2(acc[mt][nt][0], acc[mt][nt][1]);
            if (r1 < M)
                *reinterpret_cast<unsigned*>(g_xw_h + (size_t)r1 * OUT_CH + col) =
                    pack_h2(acc[mt][nt][2], acc[mt][nt][3]);
        }
    }
}

// ---------------------------------------------------------------------------
// CSR build. g_cnt / g_total are zero on entry (zeroed by previous aggregate;
// device globals zero-initialized at module load for the first call).
// ---------------------------------------------------------------------------
__global__ void hist_kernel(const int* __restrict__ esrc, int E)
{
    const int i = blockIdx.x * blockDim.x + threadIdx.x;
    const int base = i * 4;
    if (base + 3 < E) {
        const int4 s = *reinterpret_cast<const int4*>(esrc + base);
        atomicAdd(&g_cnt[s.x], 1);
        atomicAdd(&g_cnt[s.y], 1);
        atomicAdd(&g_cnt[s.z], 1);
        atomicAdd(&g_cnt[s.w], 1);
    } else {
        for (int j = base; j < E; ++j)
            atomicAdd(&g_cnt[esrc[j]], 1);
    }
}

__global__ void alloc_kernel(int N)
{
    int n = blockIdx.x * blockDim.x + threadIdx.x;
    int lane = threadIdx.x & 31;
    int c = (n < N) ? g_cnt[n] : 0;

    int scan = c;
    #pragma unroll
    for (int o = 1; o < 32; o <<= 1) {
        int t = __shfl_up_sync(0xffffffffu, scan, o);
        if (lane >= o) scan += t;
    }
    int warp_tot = __shfl_sync(0xffffffffu, scan, 31);
    int base = 0;
    if (lane == 31) base = atomicAdd(&g_total, warp_tot);
    base = __shfl_sync(0xffffffffu, base, 31);

    if (n < N) {
        int st = base + (scan - c);
        g_row_start[n] = st;
        g_cursor[n]    = st;
    }
}

__global__ void bin_kernel(const int* __restrict__ esrc, const int* __restrict__ edst,
                           const float* __restrict__ evals, int E)
{
    const int i = blockIdx.x * blockDim.x + threadIdx.x;
    const int base = i * 4;
    if (base + 3 < E) {
        const int4   s = *reinterpret_cast<const int4*>(esrc + base);
        const int4   d = *reinterpret_cast<const int4*>(edst + base);
        const float4 v = *reinterpret_cast<const float4*>(evals + base);
        int p;
        p = atomicAdd(&g_cursor[s.x], 1); g_edges[p] = make_float2(__int_as_float(d.x), v.x);
        p = atomicAdd(&g_cursor[s.y], 1); g_edges[p] = make_float2(__int_as_float(d.y), v.y);
        p = atomicAdd(&g_cursor[s.z], 1); g_edges[p] = make_float2(__int_as_float(d.z), v.z);
        p = atomicAdd(&g_cursor[s.w], 1); g_edges[p] = make_float2(__int_as_float(d.w), v.w);
    } else {
        for (int j = base; j < E; ++j) {
            int p = atomicAdd(&g_cursor[esrc[j]], 1);
            g_edges[p] = make_float2(__int_as_float(edst[j]), evals[j]);
        }
    }
}

// ---------------------------------------------------------------------------
// Aggregation: one warp per node, fp16 gathers, fp32 accumulators.
// Also restores g_cnt = 0 and g_total = 0 for the next execution.
// ---------------------------------------------------------------------------
__global__ __launch_bounds__(256)
void aggregate_kernel(const float* __restrict__ bias, float* __restrict__ out, int N)
{
    const int node = (blockIdx.x * blockDim.x + threadIdx.x) >> 5;
    const int lane = threadIdx.x & 31;
    if (node >= N) return;

    const int start = g_row_start[node];
    const int deg   = g_cnt[node];
    if (lane == 0) {
        g_cnt[node] = 0;
        if (node == 0) g_total = 0;
    }

    float4 acc = make_float4(0.f, 0.f, 0.f, 0.f);

    for (int base = 0; base < deg; base += 32) {
        const int n = min(32, deg - base);
        float2 meta = make_float2(0.f, 0.f);
        if (lane < n)
            meta = g_edges[start + base + lane];

        #pragma unroll 4
        for (int i = 0; i < n; ++i) {
            const int   dst = __shfl_sync(0xffffffffu, __float_as_int(meta.x), i);
            const float v   = __shfl_sync(0xffffffffu, meta.y, i);

            const uint2 raw = __ldg(reinterpret_cast<const uint2*>(
                                        g_xw_h + (size_t)dst * OUT_CH) + lane);
            const __half2 h0 = *reinterpret_cast<const __half2*>(&raw.x);
            const __half2 h1 = *reinterpret_cast<const __half2*>(&raw.y);
            const float2 f0 = __half22float2(h0);
            const float2 f1 = __half22float2(h1);

            acc.x = fmaf(v, f0.x, acc.x);
            acc.y = fmaf(v, f0.y, acc.y);
            acc.z = fmaf(v, f1.x, acc.z);
            acc.w = fmaf(v, f1.y, acc.w);
        }
    }

    const float4 b = __ldg(reinterpret_cast<const float4*>(bias) + lane);
    acc.x += b.x; acc.y += b.y; acc.z += b.z; acc.w += b.w;

    *(reinterpret_cast<float4*>(out + (size_t)node * OUT_CH) + lane) = acc;
}

// ---------------------------------------------------------------------------
extern "C" void kernel_launch(void* const* d_in, const int* in_sizes, int n_in,
                              void* d_out, int out_size)
{
    const float* x     = (const float*)d_in[0];   // [N, 256]
    const int*   esrc  = (const int*)  d_in[1];   // [E]
    const int*   edst  = (const int*)  d_in[2];   // [E]
    const float* evals = (const float*)d_in[3];   // [E]
    const float* W     = (const float*)d_in[4];   // [256, 128]
    const float* bias  = (const float*)d_in[5];   // [128]
    float* out = (float*)d_out;                   // [N, 128]

    const int M = in_sizes[0] / IN_CH;            // 100000
    const int E = in_sizes[1];                    // 3200000

    // ---- fork: CSR build on side stream, GEMM path on main stream ----
    cudaEventRecord(g_hx.e1, 0);
    cudaStreamWaitEvent(g_hx.s2, g_hx.e1, 0);

    {   // side stream: hist -> alloc -> bin
        const int e4blocks = ((E + 3) / 4 + 255) / 256;
        hist_kernel<<<e4blocks, 256, 0, g_hx.s2>>>(esrc, E);
        alloc_kernel<<<(M + 255) / 256, 256, 0, g_hx.s2>>>(M);
        bin_kernel<<<e4blocks, 256, 0, g_hx.s2>>>(esrc, edst, evals, E);
        cudaEventRecord(g_hx.e2, g_hx.s2);
    }

    // main stream: W convert + GEMM
    convert_w_kernel<<<(IN_CH * OUT_CH + 255) / 256, 256>>>(W);
    gemm_f16_kernel<<<(M + 127) / 128, 256>>>(x, M);

    // join, then aggregate
    cudaStreamWaitEvent(0, g_hx.e2, 0);
    {
        long long threads = (long long)M * 32;
        int blocks = (int)((threads + 255) / 256);
        aggregate_kernel<<<blocks, 256>>>(bias, out, M);
    }
}